// round 12
// baseline (speedup 1.0000x reference)
#include <cuda_runtime.h>
#include <cstdint>
#include <math.h>

// Problem constants
#define T_STEPS 1024
#define BATCH   16
#define HID     512
#define NBLK    128    // symmetric blocks: each owns 4 h0-units AND 4 h1-units
#define RED_P   20     // padded row stride (floats): 80 B, 16B-aligned for float4

typedef unsigned long long ull;

// ------------------------- static device scratch -------------------------
__device__ float g_gx[(size_t)BATCH * T_STEPS * 4 * HID];   // layer-0 gate preactivations (input part)
__device__ float g_h0T[2][HID / 2][32];                     // h0 double-buffered, transposed k-pairs
__device__ float g_h1T[2][HID / 2][32];                     // h1 double-buffered
__device__ unsigned g_flag0[NBLK * 32];                     // h0 publish flags, 128B stride
__device__ unsigned g_flag1[NBLK * 32];                     // h1 publish flags

// ------------------------- helpers -------------------------
__device__ __forceinline__ ull ffma2(ull a, ull b, ull c) {
    ull d;
    asm("fma.rn.f32x2 %0, %1, %2, %3;" : "=l"(d) : "l"(a), "l"(b), "l"(c));
    return d;
}
__device__ __forceinline__ ull splat2(float a) {
    ull d;
    asm("mov.b64 %0, {%1, %1};" : "=l"(d) : "f"(a));
    return d;
}
__device__ __forceinline__ float2 unpack2(ull v) {
    float2 f;
    asm("mov.b64 {%0, %1}, %2;" : "=f"(f.x), "=f"(f.y) : "l"(v));
    return f;
}
__device__ __forceinline__ float sigm(float x) { return 1.0f / (1.0f + __expf(-x)); }
__device__ __forceinline__ void st_release_gpu(unsigned* p, unsigned v) {
    asm volatile("st.release.gpu.global.u32 [%0], %1;" :: "l"(p), "r"(v) : "memory");
}
__device__ __forceinline__ unsigned ld_acquire_gpu(const unsigned* p) {
    unsigned v;
    asm volatile("ld.acquire.gpu.global.u32 %0, [%1];" : "=r"(v) : "l"(p) : "memory");
    return v;
}

// ------------------------- flag reset -------------------------
__global__ void init_flags() {
    g_flag0[threadIdx.x * 32] = 0u;
    g_flag1[threadIdx.x * 32] = 0u;
}

// ------------------------- big GEMM: g_gx = x @ W_ih0^T + b_ih0 -------------------------
__global__ __launch_bounds__(256) void gemm_gates(const float* __restrict__ A,
                                                  const float* __restrict__ W,
                                                  const float* __restrict__ bias) {
    __shared__ float As[16][128];
    __shared__ float Bs[16][128];
    const int tid = threadIdx.x;
    const int tx = tid & 15, ty = tid >> 4;
    const int bn = blockIdx.x, bm = blockIdx.y;
    const float* Ab = A + (size_t)bm * 128 * 512;
    const float* Wb = W + (size_t)bn * 128 * 512;
    const int lr = tid >> 2;
    const int lc = (tid & 3) << 2;

    ull acc2[4][8];
#pragma unroll
    for (int i = 0; i < 4; i++)
#pragma unroll
        for (int j = 0; j < 8; j++) acc2[i][j] = 0ull;

    for (int k0 = 0; k0 < 512; k0 += 16) {
        float4 a0 = *(const float4*)(Ab + (size_t)lr * 512 + k0 + lc);
        float4 a1 = *(const float4*)(Ab + (size_t)(lr + 64) * 512 + k0 + lc);
        float4 w0 = *(const float4*)(Wb + (size_t)lr * 512 + k0 + lc);
        float4 w1 = *(const float4*)(Wb + (size_t)(lr + 64) * 512 + k0 + lc);
        __syncthreads();
        As[lc + 0][lr] = a0.x; As[lc + 1][lr] = a0.y; As[lc + 2][lr] = a0.z; As[lc + 3][lr] = a0.w;
        As[lc + 0][lr + 64] = a1.x; As[lc + 1][lr + 64] = a1.y; As[lc + 2][lr + 64] = a1.z; As[lc + 3][lr + 64] = a1.w;
        Bs[lc + 0][lr] = w0.x; Bs[lc + 1][lr] = w0.y; Bs[lc + 2][lr] = w0.z; Bs[lc + 3][lr] = w0.w;
        Bs[lc + 0][lr + 64] = w1.x; Bs[lc + 1][lr + 64] = w1.y; Bs[lc + 2][lr + 64] = w1.z; Bs[lc + 3][lr + 64] = w1.w;
        __syncthreads();
#pragma unroll
        for (int k = 0; k < 16; k++) {
            ulonglong2 av0 = *(const ulonglong2*)&As[k][ty * 8];
            ulonglong2 av1 = *(const ulonglong2*)&As[k][ty * 8 + 4];
            float4 bv0 = *(const float4*)&Bs[k][tx * 8];
            float4 bv1 = *(const float4*)&Bs[k][tx * 8 + 4];
            ull ap[4] = {av0.x, av0.y, av1.x, av1.y};
            ull bp[8] = {splat2(bv0.x), splat2(bv0.y), splat2(bv0.z), splat2(bv0.w),
                         splat2(bv1.x), splat2(bv1.y), splat2(bv1.z), splat2(bv1.w)};
#pragma unroll
            for (int i = 0; i < 4; i++)
#pragma unroll
                for (int j = 0; j < 8; j++) acc2[i][j] = ffma2(ap[i], bp[j], acc2[i][j]);
        }
    }

    const int ncol = bn * 128 + tx * 8;
    float bb[8];
#pragma unroll
    for (int j = 0; j < 8; j++) bb[j] = bias[ncol + j];
    float* Cb = g_gx + (size_t)(bm * 128 + ty * 8) * 2048 + ncol;
#pragma unroll
    for (int i2 = 0; i2 < 4; i2++) {
        float r0[8], r1[8];
#pragma unroll
        for (int j = 0; j < 8; j++) {
            float2 v = unpack2(acc2[i2][j]);
            r0[j] = v.x + bb[j];
            r1[j] = v.y + bb[j];
        }
        float* p0 = Cb + (size_t)(2 * i2) * 2048;
        float* p1 = p0 + 2048;
        *(float4*)(p0)     = make_float4(r0[0], r0[1], r0[2], r0[3]);
        *(float4*)(p0 + 4) = make_float4(r0[4], r0[5], r0[6], r0[7]);
        *(float4*)(p1)     = make_float4(r1[0], r1[1], r1[2], r1[3]);
        *(float4*)(p1 + 4) = make_float4(r1[4], r1[5], r1[6], r1[7]);
    }
}

// ------------------------- fused symmetric 2-layer recurrence -------------------------
// 128 blocks x 256 threads. Block bi owns h0 units 4bi..4bi+3 AND h1 units 4bi..4bi+3.
// Round s: phase-L0 computes h0(s) (K=512), publishes + releases flag0 EARLY;
//          phase-L1 computes h1(s-1) (concat K=1024: [W_hh1|h1(s-2)] + [W_ih1|h0(s-1)]).
// Thread map: lane = (ks=lane>>4, row=lane&15); K-window tix = wrp*2+ks. All staging warp-local.
__global__ __launch_bounds__(256, 1) void lstm_fused(
    const float* __restrict__ w_hh0, const float* __restrict__ b_hh0,
    const float* __restrict__ w_ih1, const float* __restrict__ w_hh1,
    const float* __restrict__ b_ih1, const float* __restrict__ b_hh1,
    const float* __restrict__ h_init, const float* __restrict__ c_init,
    float* __restrict__ out) {
    extern __shared__ float smemf[];
    float* hs0  = smemf;                        // 8192 floats: h0(s-1) transposed k-pairs
    float* hs1  = smemf + 8192;                 // 8192 floats: h1(s-2)
    float* red  = smemf + 16384;                // 8*16*RED_P = 2560
    float* gbuf = smemf + 16384 + 2560;         // 256
    float* bsm  = smemf + 16384 + 2560 + 256;   // 32

    const int tid = threadIdx.x;
    const int lane = tid & 31;
    const int wrp = tid >> 5;
    const int bi = blockIdx.x;
    const int n0 = bi * 4;
    const int tix = wrp * 2 + (lane >> 4);      // K-window index 0..15
    const int row = lane & 15;                  // gate row 0..15 (gate=row>>2, unit=row&3)
    const int grow = (row >> 2) * HID + n0 + (row & 3);

    // ---- weights into registers: L0 slice 32 floats, L1 slice 64 floats ----
    ull wreg0[16], wreg1[32];
    {
        const float4* p = (const float4*)(w_hh0 + (size_t)grow * HID + tix * 32);
#pragma unroll
        for (int i = 0; i < 8; i++) {
            float4 v = __ldg(p + i);
            ulonglong2 u2 = *(ulonglong2*)&v;
            wreg0[2 * i] = u2.x; wreg0[2 * i + 1] = u2.y;
        }
    }
    {
        const float* wsrc = (tix < 8) ? (w_hh1 + (size_t)grow * HID + tix * 64)
                                      : (w_ih1 + (size_t)grow * HID + (tix - 8) * 64);
        const float4* p = (const float4*)wsrc;
#pragma unroll
        for (int i = 0; i < 16; i++) {
            float4 v = __ldg(p + i);
            ulonglong2 u2 = *(ulonglong2*)&v;
            wreg1[2 * i] = u2.x; wreg1[2 * i + 1] = u2.y;
        }
    }
    if (tid < 16) {
        bsm[tid] = __ldg(&b_hh0[(tid >> 2) * HID + n0 + (tid & 3)]);
    } else if (tid < 32) {
        int rr = tid - 16;
        int g2 = (rr >> 2) * HID + n0 + (rr & 3);
        bsm[tid] = __ldg(&b_ih1[g2]) + __ldg(&b_hh1[g2]);
    }

    float cA = 0.f, cB = 0.f;
    if (tid < 64) {
        int u = tid >> 4, b = tid & 15;
        cA = __ldg(&c_init[b * HID + n0 + u]);
        cB = __ldg(&c_init[BATCH * HID + b * HID + n0 + u]);
    }

    const int rowc = tid >> 4;   // combine-stage row 0..15
    const int bc   = tid & 15;
    const int gxoff = (rowc >> 2) * HID + n0 + (rowc & 3);

    __syncthreads();

    for (int s = 0; s <= T_STEPS; s++) {
        // prefetch gx for layer-0 step t=s (hidden under the wait)
        float gx = 0.f;
        if (s < T_STEPS)
            gx = __ldg(&g_gx[((size_t)bc * T_STEPS + s) * 2048 + gxoff]);

        // ======== phase 0: layer 0 (t = s) ========
        if (s == 0) {
            for (int i = tid; i < 8192; i += 256) {
                int k2 = i >> 5, j = i & 31;
                hs0[i] = h_init[(j >> 1) * HID + 2 * k2 + (j & 1)];
            }
            __syncthreads();
        } else {
            // wait flag0 >= s (all warps; 4 flags/lane)
            {
                const unsigned tgt = (unsigned)s;
                const unsigned* f0 = &g_flag0[lane * 32];
                const unsigned* f1 = &g_flag0[(lane + 32) * 32];
                const unsigned* f2 = &g_flag0[(lane + 64) * 32];
                const unsigned* f3 = &g_flag0[(lane + 96) * 32];
                bool ok;
                do {
                    ok = (ld_acquire_gpu(f0) >= tgt) & (ld_acquire_gpu(f1) >= tgt) &
                         (ld_acquire_gpu(f2) >= tgt) & (ld_acquire_gpu(f3) >= tgt);
                } while (!__all_sync(0xffffffffu, ok));
            }
            // warp-local stage of this warp's hs0 K-slice (256 float4)
            const float4* src = (const float4*)&g_h0T[(s - 1) & 1][0][0];
            float4* dst = (float4*)hs0;
            const int base = wrp * 256;
#pragma unroll
            for (int it = 0; it < 8; it++) {
                int idx = base + lane + it * 32;
                dst[idx] = __ldcg(src + idx);
            }
        }

        if (s < T_STEPS) {
            // L0 GEMV: 16 k-pairs per thread
            ull acc[16];
#pragma unroll
            for (int b = 0; b < 16; b++) acc[b] = 0ull;
            const ulonglong2* hb = (const ulonglong2*)(hs0 + tix * 512);
#pragma unroll
            for (int kk = 0; kk < 16; kk++) {
                const ulonglong2* hp = hb + kk * 8;
#pragma unroll
                for (int q = 0; q < 8; q++) {
                    ulonglong2 hv = hp[q];
                    acc[2 * q]     = ffma2(wreg0[kk], hv.x, acc[2 * q]);
                    acc[2 * q + 1] = ffma2(wreg0[kk], hv.y, acc[2 * q + 1]);
                }
            }
            float p[16];
#pragma unroll
            for (int b = 0; b < 16; b++) {
                float2 v = unpack2(acc[b]);
                p[b] = v.x + v.y;
            }
#pragma unroll
            for (int b = 0; b < 16; b++) p[b] += __shfl_xor_sync(0xffffffffu, p[b], 16);
            if (lane < 16) {
                float* rp = &red[(wrp * 16 + row) * RED_P];
#pragma unroll
                for (int q = 0; q < 4; q++)
                    *(float4*)&rp[q * 4] = make_float4(p[4 * q], p[4 * q + 1], p[4 * q + 2], p[4 * q + 3]);
            }
            __syncthreads();
            {
                float sum = gx + bsm[rowc];
#pragma unroll
                for (int w = 0; w < 8; w++) sum += red[(w * 16 + rowc) * RED_P + bc];
                gbuf[rowc * 16 + bc] = (rowc >= 8 && rowc < 12) ? tanhf(sum) : sigm(sum);
            }
            __syncthreads();
            if (tid < 64) {
                int u = tid >> 4, b = tid & 15;
                float iv = gbuf[(0 + u) * 16 + b];
                float fv = gbuf[(4 + u) * 16 + b];
                float gv = gbuf[(8 + u) * 16 + b];
                float ov = gbuf[(12 + u) * 16 + b];
                cA = fv * cA + iv * gv;
                float h = ov * tanhf(cA);
                int n = n0 + u;
                g_h0T[s & 1][n >> 1][b * 2 + (n & 1)] = h;
                if (s == T_STEPS - 1) out[b * HID + n] = h;
            }
            __syncthreads();
            if (tid == 0) st_release_gpu(&g_flag0[bi * 32], (unsigned)(s + 1));
        } else {
            __syncthreads();   // hs0 staged cross-warp for phase 1
        }

        // ======== phase 1: layer 1 (t = s-1) ========
        if (s >= 1) {
            if (s == 1) {
                for (int i = tid; i < 8192; i += 256) {
                    int k2 = i >> 5, j = i & 31;
                    hs1[i] = h_init[BATCH * HID + (j >> 1) * HID + 2 * k2 + (j & 1)];
                }
                __syncthreads();
            } else if (wrp < 4) {
                // only h1-half warps wait on flag1; warps 4-7 use already-staged hs0
                const unsigned tgt = (unsigned)s;
                const unsigned* f0 = &g_flag1[lane * 32];
                const unsigned* f1 = &g_flag1[(lane + 32) * 32];
                const unsigned* f2 = &g_flag1[(lane + 64) * 32];
                const unsigned* f3 = &g_flag1[(lane + 96) * 32];
                bool ok;
                do {
                    ok = (ld_acquire_gpu(f0) >= tgt) & (ld_acquire_gpu(f1) >= tgt) &
                         (ld_acquire_gpu(f2) >= tgt) & (ld_acquire_gpu(f3) >= tgt);
                } while (!__all_sync(0xffffffffu, ok));
                const float4* src = (const float4*)&g_h1T[s & 1][0][0];
                float4* dst = (float4*)hs1;
                const int base = wrp * 512;
#pragma unroll
                for (int it = 0; it < 16; it++) {
                    int idx = base + lane + it * 32;
                    dst[idx] = __ldcg(src + idx);
                }
            }

            // L1 GEMV: 32 k-pairs per thread over concat K
            {
                ull acc[16];
#pragma unroll
                for (int b = 0; b < 16; b++) acc[b] = 0ull;
                const float* hsrc = (tix < 8) ? (hs1 + tix * 1024) : (hs0 + (tix - 8) * 1024);
                const ulonglong2* hb = (const ulonglong2*)hsrc;
#pragma unroll
                for (int kk = 0; kk < 32; kk++) {
                    const ulonglong2* hp = hb + kk * 8;
#pragma unroll
                    for (int q = 0; q < 8; q++) {
                        ulonglong2 hv = hp[q];
                        acc[2 * q]     = ffma2(wreg1[kk], hv.x, acc[2 * q]);
                        acc[2 * q + 1] = ffma2(wreg1[kk], hv.y, acc[2 * q + 1]);
                    }
                }
                float p[16];
#pragma unroll
                for (int b = 0; b < 16; b++) {
                    float2 v = unpack2(acc[b]);
                    p[b] = v.x + v.y;
                }
#pragma unroll
                for (int b = 0; b < 16; b++) p[b] += __shfl_xor_sync(0xffffffffu, p[b], 16);
                if (lane < 16) {
                    float* rp = &red[(wrp * 16 + row) * RED_P];
#pragma unroll
                    for (int q = 0; q < 4; q++)
                        *(float4*)&rp[q * 4] = make_float4(p[4 * q], p[4 * q + 1], p[4 * q + 2], p[4 * q + 3]);
                }
            }
            __syncthreads();
            {
                float sum = bsm[16 + rowc];
#pragma unroll
                for (int w = 0; w < 8; w++) sum += red[(w * 16 + rowc) * RED_P + bc];
                gbuf[rowc * 16 + bc] = (rowc >= 8 && rowc < 12) ? tanhf(sum) : sigm(sum);
            }
            __syncthreads();
            if (tid < 64) {
                int u = tid >> 4, b = tid & 15;
                float iv = gbuf[(0 + u) * 16 + b];
                float fv = gbuf[(4 + u) * 16 + b];
                float gv = gbuf[(8 + u) * 16 + b];
                float ov = gbuf[(12 + u) * 16 + b];
                cB = fv * cB + iv * gv;
                float h = ov * tanhf(cB);
                int n = n0 + u;
                g_h1T[(s - 1) & 1][n >> 1][b * 2 + (n & 1)] = h;
                if (s == T_STEPS) out[BATCH * HID + b * HID + n] = h;
            }
            __syncthreads();
            if (tid == 0 && s < T_STEPS) st_release_gpu(&g_flag1[bi * 32], (unsigned)(s + 1));
        }
    }
}

// ------------------------- launch -------------------------
extern "C" void kernel_launch(void* const* d_in, const int* in_sizes, int n_in,
                              void* d_out, int out_size) {
    const float* x     = (const float*)d_in[0];
    const float* h0    = (const float*)d_in[1];
    const float* c0    = (const float*)d_in[2];
    const float* w_ih0 = (const float*)d_in[3];
    const float* w_hh0 = (const float*)d_in[4];
    const float* b_ih0 = (const float*)d_in[5];
    const float* b_hh0 = (const float*)d_in[6];
    const float* w_ih1 = (const float*)d_in[7];
    const float* w_hh1 = (const float*)d_in[8];
    const float* b_ih1 = (const float*)d_in[9];
    const float* b_hh1 = (const float*)d_in[10];
    float* out = (float*)d_out;

    const int fused_smem = (8192 + 8192 + 2560 + 256 + 32) * 4;  // 76,928 B
    cudaFuncSetAttribute(lstm_fused, cudaFuncAttributeMaxDynamicSharedMemorySize, fused_smem);

    init_flags<<<1, NBLK>>>();
    gemm_gates<<<dim3(16, 128), 256>>>(x, w_ih0, b_ih0);
    lstm_fused<<<NBLK, 256, fused_smem>>>(w_hh0, b_hh0, w_ih1, w_hh1, b_ih1, b_hh1,
                                          h0, c0, out);
}

// round 13
// speedup vs baseline: 1.2217x; 1.2217x over previous
#include <cuda_runtime.h>
#include <cstdint>
#include <math.h>

// Problem constants
#define T_STEPS 1024
#define BATCH   16
#define HID     512
#define NBLK    128    // 64 layer-0 blocks + 64 layer-1 blocks, one persistent kernel
#define RED_P   20     // padded row stride (floats): 80 B, 16B-aligned for float4

typedef unsigned long long ull;

// ------------------------- static device scratch -------------------------
__device__ float g_gx[(size_t)BATCH * T_STEPS * 4 * HID];   // layer-0 gate preactivations (input part)
__device__ float g_h0T[4][HID / 2][32];                     // h0 QUAD-buffered, transposed k-pairs
__device__ float g_h1T[2][HID / 2][32];                     // h1 double-buffered
__device__ unsigned g_flag[NBLK * 32];                      // one flag per block, 128B stride
                                                            // [0..63]=L0 blocks, [64..127]=L1 blocks

// ------------------------- helpers -------------------------
__device__ __forceinline__ ull ffma2(ull a, ull b, ull c) {
    ull d;
    asm("fma.rn.f32x2 %0, %1, %2, %3;" : "=l"(d) : "l"(a), "l"(b), "l"(c));
    return d;
}
__device__ __forceinline__ ull splat2(float a) {
    ull d;
    asm("mov.b64 %0, {%1, %1};" : "=l"(d) : "f"(a));
    return d;
}
__device__ __forceinline__ float2 unpack2(ull v) {
    float2 f;
    asm("mov.b64 {%0, %1}, %2;" : "=f"(f.x), "=f"(f.y) : "l"(v));
    return f;
}
__device__ __forceinline__ float sigm(float x) { return 1.0f / (1.0f + __expf(-x)); }
__device__ __forceinline__ void st_release_gpu(unsigned* p, unsigned v) {
    asm volatile("st.release.gpu.global.u32 [%0], %1;" :: "l"(p), "r"(v) : "memory");
}
__device__ __forceinline__ unsigned ld_acquire_gpu(const unsigned* p) {
    unsigned v;
    asm volatile("ld.acquire.gpu.global.u32 %0, [%1];" : "=r"(v) : "l"(p) : "memory");
    return v;
}

// ------------------------- big GEMM: g_gx = x @ W_ih0^T + b_ih0 -------------------------
// Block (0,0) also resets the recurrence flags (stream order protects the fused kernel).
__global__ __launch_bounds__(256) void gemm_gates(const float* __restrict__ A,
                                                  const float* __restrict__ W,
                                                  const float* __restrict__ bias) {
    if (blockIdx.x == 0 && blockIdx.y == 0 && threadIdx.x < NBLK)
        g_flag[threadIdx.x * 32] = 0u;

    __shared__ float As[16][128];
    __shared__ float Bs[16][128];
    const int tid = threadIdx.x;
    const int tx = tid & 15, ty = tid >> 4;
    const int bn = blockIdx.x, bm = blockIdx.y;
    const float* Ab = A + (size_t)bm * 128 * 512;
    const float* Wb = W + (size_t)bn * 128 * 512;
    const int lr = tid >> 2;
    const int lc = (tid & 3) << 2;

    ull acc2[4][8];
#pragma unroll
    for (int i = 0; i < 4; i++)
#pragma unroll
        for (int j = 0; j < 8; j++) acc2[i][j] = 0ull;

    for (int k0 = 0; k0 < 512; k0 += 16) {
        float4 a0 = *(const float4*)(Ab + (size_t)lr * 512 + k0 + lc);
        float4 a1 = *(const float4*)(Ab + (size_t)(lr + 64) * 512 + k0 + lc);
        float4 w0 = *(const float4*)(Wb + (size_t)lr * 512 + k0 + lc);
        float4 w1 = *(const float4*)(Wb + (size_t)(lr + 64) * 512 + k0 + lc);
        __syncthreads();
        As[lc + 0][lr] = a0.x; As[lc + 1][lr] = a0.y; As[lc + 2][lr] = a0.z; As[lc + 3][lr] = a0.w;
        As[lc + 0][lr + 64] = a1.x; As[lc + 1][lr + 64] = a1.y; As[lc + 2][lr + 64] = a1.z; As[lc + 3][lr + 64] = a1.w;
        Bs[lc + 0][lr] = w0.x; Bs[lc + 1][lr] = w0.y; Bs[lc + 2][lr] = w0.z; Bs[lc + 3][lr] = w0.w;
        Bs[lc + 0][lr + 64] = w1.x; Bs[lc + 1][lr + 64] = w1.y; Bs[lc + 2][lr + 64] = w1.z; Bs[lc + 3][lr + 64] = w1.w;
        __syncthreads();
#pragma unroll
        for (int k = 0; k < 16; k++) {
            ulonglong2 av0 = *(const ulonglong2*)&As[k][ty * 8];
            ulonglong2 av1 = *(const ulonglong2*)&As[k][ty * 8 + 4];
            float4 bv0 = *(const float4*)&Bs[k][tx * 8];
            float4 bv1 = *(const float4*)&Bs[k][tx * 8 + 4];
            ull ap[4] = {av0.x, av0.y, av1.x, av1.y};
            ull bp[8] = {splat2(bv0.x), splat2(bv0.y), splat2(bv0.z), splat2(bv0.w),
                         splat2(bv1.x), splat2(bv1.y), splat2(bv1.z), splat2(bv1.w)};
#pragma unroll
            for (int i = 0; i < 4; i++)
#pragma unroll
                for (int j = 0; j < 8; j++) acc2[i][j] = ffma2(ap[i], bp[j], acc2[i][j]);
        }
    }

    const int ncol = bn * 128 + tx * 8;
    float bb[8];
#pragma unroll
    for (int j = 0; j < 8; j++) bb[j] = bias[ncol + j];
    float* Cb = g_gx + (size_t)(bm * 128 + ty * 8) * 2048 + ncol;
#pragma unroll
    for (int i2 = 0; i2 < 4; i2++) {
        float r0[8], r1[8];
#pragma unroll
        for (int j = 0; j < 8; j++) {
            float2 v = unpack2(acc2[i2][j]);
            r0[j] = v.x + bb[j];
            r1[j] = v.y + bb[j];
        }
        float* p0 = Cb + (size_t)(2 * i2) * 2048;
        float* p1 = p0 + 2048;
        *(float4*)(p0)     = make_float4(r0[0], r0[1], r0[2], r0[3]);
        *(float4*)(p0 + 4) = make_float4(r0[4], r0[5], r0[6], r0[7]);
        *(float4*)(p1)     = make_float4(r1[0], r1[1], r1[2], r1[3]);
        *(float4*)(p1 + 4) = make_float4(r1[4], r1[5], r1[6], r1[7]);
    }
}

// ------------------------- fused 2-layer pipelined recurrence -------------------------
// Blocks 0..63: layer 0 (step t = s). Blocks 64..127: layer 1 (step t = s-1).
// Per-warp producer-scoped waits; quad-buffered h0 (slack 2 vs L1); early release
// via named barrier among the h-writing warps (CG grid-sync release pattern).
__global__ __launch_bounds__(256, 1) void lstm_fused(
    const float* __restrict__ w_hh0, const float* __restrict__ b_hh0,
    const float* __restrict__ w_ih1, const float* __restrict__ w_hh1,
    const float* __restrict__ b_ih1, const float* __restrict__ b_hh1,
    const float* __restrict__ h0in, const float* __restrict__ c0in,
    float* __restrict__ out) {
    extern __shared__ float smemf[];
    float* hs   = smemf;                       // L0: 8192 floats; L1: 16384 ([h1 | h0])
    float* red  = smemf + 16384;               // 8*32*RED_P = 5120
    float* gbuf = smemf + 16384 + 5120;        // 512
    float* bsm  = smemf + 16384 + 5120 + 512;  // 32

    const int tid = threadIdx.x;
    const int lane = tid & 31;
    const int wrp = tid >> 5;
    const bool isL1 = blockIdx.x >= 64;
    const int bi = blockIdx.x & 63;
    const int n0 = bi * 8;
    const int r = lane;                         // gate row 0..31
    const int grow = (r >> 3) * HID + n0 + (r & 7);

    // weight preload into registers
    ull wreg[64];
    if (!isL1) {
        const float4* wrow = (const float4*)(w_hh0 + (size_t)grow * HID + wrp * 64);
#pragma unroll
        for (int i = 0; i < 16; i++) {
            float4 v = __ldg(wrow + i);
            ulonglong2 uu = *(ulonglong2*)&v;
            wreg[2 * i] = uu.x;
            wreg[2 * i + 1] = uu.y;
        }
    } else {
        // concat K: warps 0-3 -> w_hh1 (h1 half); warps 4-7 -> w_ih1 (h0 half)
#pragma unroll
        for (int i = 0; i < 32; i++) {
            int k = wrp * 128 + i * 4;
            const float4* src = (k < 512)
                ? (const float4*)(w_hh1 + (size_t)grow * HID + k)
                : (const float4*)(w_ih1 + (size_t)grow * HID + (k - 512));
            float4 v = __ldg(src);
            ulonglong2 uu = *(ulonglong2*)&v;
            wreg[2 * i] = uu.x;
            wreg[2 * i + 1] = uu.y;
        }
    }
    if (tid < 32) {
        int gr2 = (tid >> 3) * HID + n0 + (tid & 7);
        bsm[tid] = isL1 ? (__ldg(&b_ih1[gr2]) + __ldg(&b_hh1[gr2])) : __ldg(&b_hh0[gr2]);
    }

    const float* hinit = h0in + (isL1 ? BATCH * HID : 0);
    const float* c0l   = c0in + (isL1 ? BATCH * HID : 0);
    float c = 0.f;
    if (tid < 128) { int u = tid >> 4, b = tid & 15; c = __ldg(&c0l[b * HID + n0 + u]); }

    const int r_a = tid >> 4;       // 0..15
    const int b0 = tid & 15;
    const int r_b = r_a + 16;       // 16..31
    const int grow_a = (r_a >> 3) * HID + n0 + (r_a & 7);
    const int grow_b = (r_b >> 3) * HID + n0 + (r_b & 7);

    __syncthreads();

    for (int s = 0; s <= T_STEPS; s++) {
        if (!isL1) {
            // ================= layer 0, step t = s =================
            if (s == T_STEPS) break;
            float gx0 = __ldg(&g_gx[((size_t)b0 * T_STEPS + s) * 2048 + grow_a]);
            float gx1 = __ldg(&g_gx[((size_t)b0 * T_STEPS + s) * 2048 + grow_b]);

            if (s == 0) {
                for (int i = tid; i < 8192; i += 256) {
                    int k2 = i >> 5, j = i & 31;
                    hs[i] = hinit[(j >> 1) * HID + 2 * k2 + (j & 1)];
                }
                __syncthreads();
            } else {
                // per-warp wait: own 8 L0 producers >= s; all L1 blocks >= s-2 (quad buffer)
                const unsigned tgt = (unsigned)s;
                const unsigned* f0 = &g_flag[(8 * wrp + (lane & 7)) * 32];
                const unsigned* f2 = &g_flag[(64 + 2 * lane) * 32];
                const unsigned* f3 = &g_flag[(64 + 2 * lane + 1) * 32];
                bool ok;
                do {
                    ok = (ld_acquire_gpu(f0) >= tgt) &
                         (ld_acquire_gpu(f2) + 2u >= tgt) & (ld_acquire_gpu(f3) + 2u >= tgt);
                } while (!__all_sync(0xffffffffu, ok));
                // warp-local stage of this warp's hs K-slice (256 float4)
                const float4* src = (const float4*)&g_h0T[(s - 1) & 3][0][0];
                float4* dst = (float4*)hs;
                const int base = wrp * 256;
#pragma unroll
                for (int it = 0; it < 8; it++) {
                    int idx = base + lane + it * 32;
                    dst[idx] = __ldcg(src + idx);
                }
            }

            // GEMV (warp-local K-slice)
            ull acc[16];
#pragma unroll
            for (int b = 0; b < 16; b++) acc[b] = 0ull;
            const ulonglong2* hbase = (const ulonglong2*)(hs + (wrp * 32) * 32);
#pragma unroll
            for (int kk = 0; kk < 32; kk++) {
                const ulonglong2* hp = hbase + kk * 8;
#pragma unroll
                for (int q = 0; q < 8; q++) {
                    ulonglong2 hv = hp[q];
                    acc[2 * q]     = ffma2(wreg[kk], hv.x, acc[2 * q]);
                    acc[2 * q + 1] = ffma2(wreg[kk], hv.y, acc[2 * q + 1]);
                }
            }
            float p[16];
#pragma unroll
            for (int b = 0; b < 16; b++) {
                float2 v = unpack2(acc[b]);
                p[b] = v.x + v.y;
            }
            {
                float* rp = &red[(wrp * 32 + r) * RED_P];
#pragma unroll
                for (int q = 0; q < 4; q++)
                    *(float4*)&rp[q * 4] = make_float4(p[4 * q], p[4 * q + 1], p[4 * q + 2], p[4 * q + 3]);
            }
            __syncthreads();

            // combine + activations
            {
                float s0 = gx0 + bsm[r_a];
                float s1 = gx1 + bsm[r_b];
#pragma unroll
                for (int si = 0; si < 8; si++) {
                    s0 += red[(si * 32 + r_a) * RED_P + b0];
                    s1 += red[(si * 32 + r_b) * RED_P + b0];
                }
                float a0 = sigm(s0);
                float a1 = (r_b < 24) ? tanhf(s1) : sigm(s1);
                gbuf[r_a * 16 + b0] = a0;
                gbuf[r_b * 16 + b0] = a1;
            }
            __syncthreads();

            // cell update + early release (warps 0-3 only; warps 4-7 fall through)
            if (tid < 128) {
                int u = tid >> 4, b = tid & 15;
                float iv = gbuf[(0 + u) * 16 + b];
                float fv = gbuf[(8 + u) * 16 + b];
                float gv = gbuf[(16 + u) * 16 + b];
                float ov = gbuf[(24 + u) * 16 + b];
                c = fv * c + iv * gv;
                float h = ov * tanhf(c);
                int n = n0 + u;
                g_h0T[s & 3][n >> 1][b * 2 + (n & 1)] = h;
                if (s == T_STEPS - 1) out[b * HID + n] = h;
                asm volatile("bar.sync 1, 128;" ::: "memory");
                if (tid == 0) st_release_gpu(&g_flag[bi * 32], (unsigned)(s + 1));
            }
        } else {
            // ================= layer 1, step t = s-1 =================
            if (s == 0) continue;

            if (s == 1) {
                for (int i = tid; i < 8192; i += 256) {
                    int k2 = i >> 5, j = i & 31;
                    hs[i] = hinit[(j >> 1) * HID + 2 * k2 + (j & 1)];
                }
                __syncthreads();
            } else if (wrp < 4) {
                // h1 half: wait own 16 L1 producers >= s
                const unsigned tgt = (unsigned)s;
                const unsigned* f0 = &g_flag[(64 + wrp * 16 + (lane & 15)) * 32];
                bool ok;
                do { ok = (ld_acquire_gpu(f0) >= tgt); } while (!__all_sync(0xffffffffu, ok));
                const float4* src = (const float4*)&g_h1T[s & 1][0][0];
                float4* dst = (float4*)hs;
                const int base = wrp * 512;
#pragma unroll
                for (int it = 0; it < 16; it++) {
                    int idx = base + lane + it * 32;
                    dst[idx] = __ldcg(src + idx);
                }
            }
            if (wrp >= 4) {
                // h0 half: wait own 16 L0 producers >= s
                const unsigned tgt = (unsigned)s;
                const unsigned* f0 = &g_flag[((wrp - 4) * 16 + (lane & 15)) * 32];
                bool ok;
                do { ok = (ld_acquire_gpu(f0) >= tgt); } while (!__all_sync(0xffffffffu, ok));
                const float4* src = (const float4*)&g_h0T[(s - 1) & 3][0][0];
                float4* dst = (float4*)(hs + 8192);
                const int base = (wrp - 4) * 512;
#pragma unroll
                for (int it = 0; it < 16; it++) {
                    int idx = base + lane + it * 32;
                    dst[idx] = __ldcg(src + idx);
                }
            }

            // GEMV (warp-local 128-k slice of concat K)
            ull acc[16];
#pragma unroll
            for (int b = 0; b < 16; b++) acc[b] = 0ull;
            const ulonglong2* hbase = (const ulonglong2*)(hs + (wrp * 64) * 32);
#pragma unroll
            for (int kk = 0; kk < 64; kk++) {
                const ulonglong2* hp = hbase + kk * 8;
#pragma unroll
                for (int q = 0; q < 8; q++) {
                    ulonglong2 hv = hp[q];
                    acc[2 * q]     = ffma2(wreg[kk], hv.x, acc[2 * q]);
                    acc[2 * q + 1] = ffma2(wreg[kk], hv.y, acc[2 * q + 1]);
                }
            }
            float p[16];
#pragma unroll
            for (int b = 0; b < 16; b++) {
                float2 v = unpack2(acc[b]);
                p[b] = v.x + v.y;
            }
            {
                float* rp = &red[(wrp * 32 + r) * RED_P];
#pragma unroll
                for (int q = 0; q < 4; q++)
                    *(float4*)&rp[q * 4] = make_float4(p[4 * q], p[4 * q + 1], p[4 * q + 2], p[4 * q + 3]);
            }
            __syncthreads();

            // combine + activations
            {
                float s0 = bsm[r_a];
                float s1 = bsm[r_b];
#pragma unroll
                for (int si = 0; si < 8; si++) {
                    s0 += red[(si * 32 + r_a) * RED_P + b0];
                    s1 += red[(si * 32 + r_b) * RED_P + b0];
                }
                float a0 = sigm(s0);
                float a1 = (r_b < 24) ? tanhf(s1) : sigm(s1);
                gbuf[r_a * 16 + b0] = a0;
                gbuf[r_b * 16 + b0] = a1;
            }
            __syncthreads();

            // cell update + early release (warps 0-3)
            if (tid < 128) {
                int u = tid >> 4, b = tid & 15;
                float iv = gbuf[(0 + u) * 16 + b];
                float fv = gbuf[(8 + u) * 16 + b];
                float gv = gbuf[(16 + u) * 16 + b];
                float ov = gbuf[(24 + u) * 16 + b];
                c = fv * c + iv * gv;
                float h = ov * tanhf(c);
                int n = n0 + u;
                g_h1T[(s - 1) & 1][n >> 1][b * 2 + (n & 1)] = h;
                if (s == T_STEPS) out[BATCH * HID + b * HID + n] = h;
                asm volatile("bar.sync 1, 128;" ::: "memory");
                if (tid == 0 && s < T_STEPS)
                    st_release_gpu(&g_flag[(64 + bi) * 32], (unsigned)(s + 1));
            }
        }
    }
}

// ------------------------- launch -------------------------
extern "C" void kernel_launch(void* const* d_in, const int* in_sizes, int n_in,
                              void* d_out, int out_size) {
    const float* x     = (const float*)d_in[0];
    const float* h0    = (const float*)d_in[1];
    const float* c0    = (const float*)d_in[2];
    const float* w_ih0 = (const float*)d_in[3];
    const float* w_hh0 = (const float*)d_in[4];
    const float* b_ih0 = (const float*)d_in[5];
    const float* b_hh0 = (const float*)d_in[6];
    const float* w_ih1 = (const float*)d_in[7];
    const float* w_hh1 = (const float*)d_in[8];
    const float* b_ih1 = (const float*)d_in[9];
    const float* b_hh1 = (const float*)d_in[10];
    float* out = (float*)d_out;

    const int fused_smem = (16384 + 5120 + 512 + 32) * 4;  // 88,192 B
    cudaFuncSetAttribute(lstm_fused, cudaFuncAttributeMaxDynamicSharedMemorySize, fused_smem);

    gemm_gates<<<dim3(16, 128), 256>>>(x, w_ih0, b_ih0);
    lstm_fused<<<NBLK, 256, fused_smem>>>(w_hh0, b_hh0, w_ih1, w_hh1, b_ih1, b_hh1,
                                          h0, c0, out);
}

// round 16
// speedup vs baseline: 1.2639x; 1.0345x over previous
#include <cuda_runtime.h>
#include <cstdint>
#include <math.h>

// Problem constants
#define T_STEPS 1024
#define BATCH   16
#define HID     512
#define NBLK    128    // 64 layer-0 blocks + 64 layer-1 blocks, one persistent kernel
#define RED_P   20     // padded row stride (floats): 80 B, 16B-aligned for float4

typedef unsigned long long ull;

// ------------------------- static device scratch -------------------------
__device__ float g_gx[(size_t)BATCH * T_STEPS * 4 * HID];   // layer-0 gate preactivations (input part)
__device__ float g_h0T[4][HID / 2][32];                     // h0 QUAD-buffered, transposed k-pairs
__device__ float g_h1T[2][HID / 2][32];                     // h1 double-buffered
__device__ unsigned g_flag[NBLK * 32];                      // one flag per block, 128B stride
                                                            // [0..63]=L0 blocks, [64..127]=L1 blocks

// ------------------------- helpers -------------------------
__device__ __forceinline__ ull ffma2(ull a, ull b, ull c) {
    ull d;
    asm("fma.rn.f32x2 %0, %1, %2, %3;" : "=l"(d) : "l"(a), "l"(b), "l"(c));
    return d;
}
__device__ __forceinline__ ull splat2(float a) {
    ull d;
    asm("mov.b64 %0, {%1, %1};" : "=l"(d) : "f"(a));
    return d;
}
__device__ __forceinline__ float2 unpack2(ull v) {
    float2 f;
    asm("mov.b64 {%0, %1}, %2;" : "=f"(f.x), "=f"(f.y) : "l"(v));
    return f;
}
__device__ __forceinline__ float sigm(float x) { return 1.0f / (1.0f + __expf(-x)); }
__device__ __forceinline__ void st_release_gpu(unsigned* p, unsigned v) {
    asm volatile("st.release.gpu.global.u32 [%0], %1;" :: "l"(p), "r"(v) : "memory");
}
__device__ __forceinline__ unsigned ld_acquire_gpu(const unsigned* p) {
    unsigned v;
    asm volatile("ld.acquire.gpu.global.u32 %0, [%1];" : "=r"(v) : "l"(p) : "memory");
    return v;
}

// ------------------------- big GEMM: g_gx = x @ W_ih0^T + b_ih0 -------------------------
// Block (0,0) also resets the recurrence flags (stream order protects the fused kernel).
__global__ __launch_bounds__(256) void gemm_gates(const float* __restrict__ A,
                                                  const float* __restrict__ W,
                                                  const float* __restrict__ bias) {
    if (blockIdx.x == 0 && blockIdx.y == 0 && threadIdx.x < NBLK)
        g_flag[threadIdx.x * 32] = 0u;

    __shared__ float As[16][128];
    __shared__ float Bs[16][128];
    const int tid = threadIdx.x;
    const int tx = tid & 15, ty = tid >> 4;
    const int bn = blockIdx.x, bm = blockIdx.y;
    const float* Ab = A + (size_t)bm * 128 * 512;
    const float* Wb = W + (size_t)bn * 128 * 512;
    const int lr = tid >> 2;
    const int lc = (tid & 3) << 2;

    ull acc2[4][8];
#pragma unroll
    for (int i = 0; i < 4; i++)
#pragma unroll
        for (int j = 0; j < 8; j++) acc2[i][j] = 0ull;

    for (int k0 = 0; k0 < 512; k0 += 16) {
        float4 a0 = *(const float4*)(Ab + (size_t)lr * 512 + k0 + lc);
        float4 a1 = *(const float4*)(Ab + (size_t)(lr + 64) * 512 + k0 + lc);
        float4 w0 = *(const float4*)(Wb + (size_t)lr * 512 + k0 + lc);
        float4 w1 = *(const float4*)(Wb + (size_t)(lr + 64) * 512 + k0 + lc);
        __syncthreads();
        As[lc + 0][lr] = a0.x; As[lc + 1][lr] = a0.y; As[lc + 2][lr] = a0.z; As[lc + 3][lr] = a0.w;
        As[lc + 0][lr + 64] = a1.x; As[lc + 1][lr + 64] = a1.y; As[lc + 2][lr + 64] = a1.z; As[lc + 3][lr + 64] = a1.w;
        Bs[lc + 0][lr] = w0.x; Bs[lc + 1][lr] = w0.y; Bs[lc + 2][lr] = w0.z; Bs[lc + 3][lr] = w0.w;
        Bs[lc + 0][lr + 64] = w1.x; Bs[lc + 1][lr + 64] = w1.y; Bs[lc + 2][lr + 64] = w1.z; Bs[lc + 3][lr + 64] = w1.w;
        __syncthreads();
#pragma unroll
        for (int k = 0; k < 16; k++) {
            ulonglong2 av0 = *(const ulonglong2*)&As[k][ty * 8];
            ulonglong2 av1 = *(const ulonglong2*)&As[k][ty * 8 + 4];
            float4 bv0 = *(const float4*)&Bs[k][tx * 8];
            float4 bv1 = *(const float4*)&Bs[k][tx * 8 + 4];
            ull ap[4] = {av0.x, av0.y, av1.x, av1.y};
            ull bp[8] = {splat2(bv0.x), splat2(bv0.y), splat2(bv0.z), splat2(bv0.w),
                         splat2(bv1.x), splat2(bv1.y), splat2(bv1.z), splat2(bv1.w)};
#pragma unroll
            for (int i = 0; i < 4; i++)
#pragma unroll
                for (int j = 0; j < 8; j++) acc2[i][j] = ffma2(ap[i], bp[j], acc2[i][j]);
        }
    }

    const int ncol = bn * 128 + tx * 8;
    float bb[8];
#pragma unroll
    for (int j = 0; j < 8; j++) bb[j] = bias[ncol + j];
    float* Cb = g_gx + (size_t)(bm * 128 + ty * 8) * 2048 + ncol;
#pragma unroll
    for (int i2 = 0; i2 < 4; i2++) {
        float r0[8], r1[8];
#pragma unroll
        for (int j = 0; j < 8; j++) {
            float2 v = unpack2(acc2[i2][j]);
            r0[j] = v.x + bb[j];
            r1[j] = v.y + bb[j];
        }
        float* p0 = Cb + (size_t)(2 * i2) * 2048;
        float* p1 = p0 + 2048;
        *(float4*)(p0)     = make_float4(r0[0], r0[1], r0[2], r0[3]);
        *(float4*)(p0 + 4) = make_float4(r0[4], r0[5], r0[6], r0[7]);
        *(float4*)(p1)     = make_float4(r1[0], r1[1], r1[2], r1[3]);
        *(float4*)(p1 + 4) = make_float4(r1[4], r1[5], r1[6], r1[7]);
    }
}

// ------------------------- fused 2-layer pipelined recurrence -------------------------
// Blocks 0..63: layer 0 (step t = s). Blocks 64..127: layer 1 (step t = s-1).
// Per-warp producer-scoped waits; quad-buffered h0 (slack 2 vs L1); early release
// via named barrier among the h-writing warps. Reduction buffer double-buffered by
// step parity (2 x 5120 floats); combine+activation+cell fused into one 128-thread stage.
__global__ __launch_bounds__(256, 1) void lstm_fused(
    const float* __restrict__ w_hh0, const float* __restrict__ b_hh0,
    const float* __restrict__ w_ih1, const float* __restrict__ w_hh1,
    const float* __restrict__ b_ih1, const float* __restrict__ b_hh1,
    const float* __restrict__ h0in, const float* __restrict__ c0in,
    float* __restrict__ out) {
    extern __shared__ float smemf[];
    float* hs   = smemf;                        // L0: 8192 floats; L1: 16384 ([h1 | h0])
    float* red  = smemf + 16384;                // 2 x (8*32*RED_P) = 2 x 5120 (step-parity)
    float* bsm  = smemf + 16384 + 10240;        // 32

    const int tid = threadIdx.x;
    const int lane = tid & 31;
    const int wrp = tid >> 5;
    const bool isL1 = blockIdx.x >= 64;
    const int bi = blockIdx.x & 63;
    const int n0 = bi * 8;
    const int r = lane;                         // gate row 0..31
    const int grow = (r >> 3) * HID + n0 + (r & 7);

    // weight preload into registers
    ull wreg[64];
    if (!isL1) {
        const float4* wrow = (const float4*)(w_hh0 + (size_t)grow * HID + wrp * 64);
#pragma unroll
        for (int i = 0; i < 16; i++) {
            float4 v = __ldg(wrow + i);
            ulonglong2 uu = *(ulonglong2*)&v;
            wreg[2 * i] = uu.x;
            wreg[2 * i + 1] = uu.y;
        }
    } else {
        // concat K: warps 0-3 -> w_hh1 (h1 half); warps 4-7 -> w_ih1 (h0 half)
#pragma unroll
        for (int i = 0; i < 32; i++) {
            int k = wrp * 128 + i * 4;
            const float4* src = (k < 512)
                ? (const float4*)(w_hh1 + (size_t)grow * HID + k)
                : (const float4*)(w_ih1 + (size_t)grow * HID + (k - 512));
            float4 v = __ldg(src);
            ulonglong2 uu = *(ulonglong2*)&v;
            wreg[2 * i] = uu.x;
            wreg[2 * i + 1] = uu.y;
        }
    }
    if (tid < 32) {
        int gr2 = (tid >> 3) * HID + n0 + (tid & 7);
        bsm[tid] = isL1 ? (__ldg(&b_ih1[gr2]) + __ldg(&b_hh1[gr2])) : __ldg(&b_hh0[gr2]);
    }

    const float* hinit = h0in + (isL1 ? BATCH * HID : 0);
    const float* c0l   = c0in + (isL1 ? BATCH * HID : 0);
    float c = 0.f;
    if (tid < 128) { int u = tid >> 4, b = tid & 15; c = __ldg(&c0l[b * HID + n0 + u]); }

    const int ue = tid >> 4;        // epilogue unit 0..7 (tid<128)
    const int be = tid & 15;        // epilogue batch

    __syncthreads();

    for (int s = 0; s <= T_STEPS; s++) {
        float* redS = red + (s & 1) * 5120;

        if (!isL1) {
            // ================= layer 0, step t = s =================
            if (s == T_STEPS) break;
            float gxi = 0.f, gxf = 0.f, gxg = 0.f, gxo = 0.f;
            if (tid < 128) {
                const float* gp = &g_gx[((size_t)be * T_STEPS + s) * 2048 + n0 + ue];
                gxi = __ldg(gp);
                gxf = __ldg(gp + 512);
                gxg = __ldg(gp + 1024);
                gxo = __ldg(gp + 1536);
            }

            if (s == 0) {
                for (int i = tid; i < 8192; i += 256) {
                    int k2 = i >> 5, j = i & 31;
                    hs[i] = hinit[(j >> 1) * HID + 2 * k2 + (j & 1)];
                }
                __syncthreads();
            } else {
                // per-warp wait: own 8 L0 producers >= s; all L1 blocks >= s-2 (quad buffer)
                const unsigned tgt = (unsigned)s;
                const unsigned* f0 = &g_flag[(8 * wrp + (lane & 7)) * 32];
                const unsigned* f2 = &g_flag[(64 + 2 * lane) * 32];
                const unsigned* f3 = &g_flag[(64 + 2 * lane + 1) * 32];
                bool ok;
                do {
                    ok = (ld_acquire_gpu(f0) >= tgt) &
                         (ld_acquire_gpu(f2) + 2u >= tgt) & (ld_acquire_gpu(f3) + 2u >= tgt);
                } while (!__all_sync(0xffffffffu, ok));
                // warp-local stage of this warp's hs K-slice (256 float4)
                const float4* src = (const float4*)&g_h0T[(s - 1) & 3][0][0];
                float4* dst = (float4*)hs;
                const int base = wrp * 256;
#pragma unroll
                for (int it = 0; it < 8; it++) {
                    int idx = base + lane + it * 32;
                    dst[idx] = __ldcg(src + idx);
                }
            }

            // GEMV (warp-local K-slice)
            ull acc[16];
#pragma unroll
            for (int b = 0; b < 16; b++) acc[b] = 0ull;
            const ulonglong2* hbase = (const ulonglong2*)(hs + (wrp * 32) * 32);
#pragma unroll
            for (int kk = 0; kk < 32; kk++) {
                const ulonglong2* hp = hbase + kk * 8;
#pragma unroll
                for (int q = 0; q < 8; q++) {
                    ulonglong2 hv = hp[q];
                    acc[2 * q]     = ffma2(wreg[kk], hv.x, acc[2 * q]);
                    acc[2 * q + 1] = ffma2(wreg[kk], hv.y, acc[2 * q + 1]);
                }
            }
            float p[16];
#pragma unroll
            for (int b = 0; b < 16; b++) {
                float2 v = unpack2(acc[b]);
                p[b] = v.x + v.y;
            }
            {
                float* rp = &redS[(wrp * 32 + r) * RED_P];
#pragma unroll
                for (int q = 0; q < 4; q++)
                    *(float4*)&rp[q * 4] = make_float4(p[4 * q], p[4 * q + 1], p[4 * q + 2], p[4 * q + 3]);
            }
            __syncthreads();

            // fused combine + activations + cell update (128 threads)
            if (tid < 128) {
                float s_i = gxi + bsm[ue];
                float s_f = gxf + bsm[8 + ue];
                float s_g = gxg + bsm[16 + ue];
                float s_o = gxo + bsm[24 + ue];
#pragma unroll
                for (int w = 0; w < 8; w++) {
                    const float* rw = &redS[(w * 32) * RED_P + be];
                    s_i += rw[ue * RED_P];
                    s_f += rw[(8 + ue) * RED_P];
                    s_g += rw[(16 + ue) * RED_P];
                    s_o += rw[(24 + ue) * RED_P];
                }
                float iv = sigm(s_i), fv = sigm(s_f), gv = tanhf(s_g), ov = sigm(s_o);
                c = fv * c + iv * gv;
                float h = ov * tanhf(c);
                int n = n0 + ue;
                g_h0T[s & 3][n >> 1][be * 2 + (n & 1)] = h;
                if (s == T_STEPS - 1) out[be * HID + n] = h;
                asm volatile("bar.sync 1, 128;" ::: "memory");
                if (tid == 0) st_release_gpu(&g_flag[bi * 32], (unsigned)(s + 1));
            }
        } else {
            // ================= layer 1, step t = s-1 =================
            if (s == 0) continue;

            if (s == 1) {
                for (int i = tid; i < 8192; i += 256) {
                    int k2 = i >> 5, j = i & 31;
                    hs[i] = hinit[(j >> 1) * HID + 2 * k2 + (j & 1)];
                }
                __syncthreads();
            } else if (wrp < 4) {
                // h1 half: wait own 16 L1 producers >= s
                const unsigned tgt = (unsigned)s;
                const unsigned* f0 = &g_flag[(64 + wrp * 16 + (lane & 15)) * 32];
                bool ok;
                do { ok = (ld_acquire_gpu(f0) >= tgt); } while (!__all_sync(0xffffffffu, ok));
                const float4* src = (const float4*)&g_h1T[s & 1][0][0];
                float4* dst = (float4*)hs;
                const int base = wrp * 512;
#pragma unroll
                for (int it = 0; it < 16; it++) {
                    int idx = base + lane + it * 32;
                    dst[idx] = __ldcg(src + idx);
                }
            }
            if (wrp >= 4) {
                // h0 half: wait own 16 L0 producers >= s
                const unsigned tgt = (unsigned)s;
                const unsigned* f0 = &g_flag[((wrp - 4) * 16 + (lane & 15)) * 32];
                bool ok;
                do { ok = (ld_acquire_gpu(f0) >= tgt); } while (!__all_sync(0xffffffffu, ok));
                const float4* src = (const float4*)&g_h0T[(s - 1) & 3][0][0];
                float4* dst = (float4*)(hs + 8192);
                const int base = (wrp - 4) * 512;
#pragma unroll
                for (int it = 0; it < 16; it++) {
                    int idx = base + lane + it * 32;
                    dst[idx] = __ldcg(src + idx);
                }
            }

            // GEMV (warp-local 128-k slice of concat K)
            ull acc[16];
#pragma unroll
            for (int b = 0; b < 16; b++) acc[b] = 0ull;
            const ulonglong2* hbase = (const ulonglong2*)(hs + (wrp * 64) * 32);
#pragma unroll
            for (int kk = 0; kk < 64; kk++) {
                const ulonglong2* hp = hbase + kk * 8;
#pragma unroll
                for (int q = 0; q < 8; q++) {
                    ulonglong2 hv = hp[q];
                    acc[2 * q]     = ffma2(wreg[kk], hv.x, acc[2 * q]);
                    acc[2 * q + 1] = ffma2(wreg[kk], hv.y, acc[2 * q + 1]);
                }
            }
            float p[16];
#pragma unroll
            for (int b = 0; b < 16; b++) {
                float2 v = unpack2(acc[b]);
                p[b] = v.x + v.y;
            }
            {
                float* rp = &redS[(wrp * 32 + r) * RED_P];
#pragma unroll
                for (int q = 0; q < 4; q++)
                    *(float4*)&rp[q * 4] = make_float4(p[4 * q], p[4 * q + 1], p[4 * q + 2], p[4 * q + 3]);
            }
            __syncthreads();

            // fused combine + activations + cell update (128 threads)
            if (tid < 128) {
                float s_i = bsm[ue];
                float s_f = bsm[8 + ue];
                float s_g = bsm[16 + ue];
                float s_o = bsm[24 + ue];
#pragma unroll
                for (int w = 0; w < 8; w++) {
                    const float* rw = &redS[(w * 32) * RED_P + be];
                    s_i += rw[ue * RED_P];
                    s_f += rw[(8 + ue) * RED_P];
                    s_g += rw[(16 + ue) * RED_P];
                    s_o += rw[(24 + ue) * RED_P];
                }
                float iv = sigm(s_i), fv = sigm(s_f), gv = tanhf(s_g), ov = sigm(s_o);
                c = fv * c + iv * gv;
                float h = ov * tanhf(c);
                int n = n0 + ue;
                g_h1T[(s - 1) & 1][n >> 1][be * 2 + (n & 1)] = h;
                if (s == T_STEPS) out[BATCH * HID + be * HID + n] = h;
                asm volatile("bar.sync 1, 128;" ::: "memory");
                if (tid == 0 && s < T_STEPS)
                    st_release_gpu(&g_flag[(64 + bi) * 32], (unsigned)(s + 1));
            }
        }
    }
}

// ------------------------- launch -------------------------
extern "C" void kernel_launch(void* const* d_in, const int* in_sizes, int n_in,
                              void* d_out, int out_size) {
    const float* x     = (const float*)d_in[0];
    const float* h0    = (const float*)d_in[1];
    const float* c0    = (const float*)d_in[2];
    const float* w_ih0 = (const float*)d_in[3];
    const float* w_hh0 = (const float*)d_in[4];
    const float* b_ih0 = (const float*)d_in[5];
    const float* b_hh0 = (const float*)d_in[6];
    const float* w_ih1 = (const float*)d_in[7];
    const float* w_hh1 = (const float*)d_in[8];
    const float* b_ih1 = (const float*)d_in[9];
    const float* b_hh1 = (const float*)d_in[10];
    float* out = (float*)d_out;

    const int fused_smem = (16384 + 10240 + 32) * 4;  // 106,624 B
    cudaFuncSetAttribute(lstm_fused, cudaFuncAttributeMaxDynamicSharedMemorySize, fused_smem);

    gemm_gates<<<dim3(16, 128), 256>>>(x, w_ih0, b_ih0);
    lstm_fused<<<NBLK, 256, fused_smem>>>(w_hh0, b_hh0, w_ih1, w_hh1, b_ih1, b_hh1,
                                          h0, c0, out);
}